// round 15
// baseline (speedup 1.0000x reference)
#include <cuda_runtime.h>
#include <math.h>

#define D 128
#define T 64
#define BATCH 512
#define EPS 1e-5f
#define FULLMASK 0xffffffffu

#define SV_STRIDE 129   // conflict-free rows AND columns (129 mod 32 = 1)
#define TB (T * BATCH)

// -------- scratch (device globals; no allocation allowed) --------
__device__ float g_outT[T * BATCH * D];      // output transposed: [t][b][d]

// -------- transpose outT [t][b][d] -> out (D,T,B); also emit h_last --------
__global__ void transpose_out_kernel(float* __restrict__ out) {
    __shared__ float tile[32][33];
    int t = blockIdx.z;
    int b0 = blockIdx.x * 32, d0 = blockIdx.y * 32;
    int tx = threadIdx.x, ty = threadIdx.y;
    const float* src = g_outT + (size_t)t * BATCH * D;
#pragma unroll
    for (int i = 0; i < 32; i += 8)
        tile[ty + i][tx] = src[(size_t)(b0 + ty + i) * D + (d0 + tx)];
    __syncthreads();
#pragma unroll
    for (int i = 0; i < 32; i += 8) {
        float val = tile[tx][ty + i];
        int d = d0 + ty + i;
        int b = b0 + tx;
        out[(size_t)d * TB + (size_t)t * BATCH + b] = val;
        if (t == T - 1)
            out[(size_t)D * TB + (size_t)d * BATCH + b] = val;
    }
}

// -------- main recurrence: 1 warp per batch column, thread owns 4 dims.
// Warps independent (no block barriers in hot loop). v is kept in TWO smem
// forms: sv (row-major, for the k*-screen's row access) and pv (column-major
// row-quads: pv[i][lane] = {v[lane][i], v[lane+32][i], v[lane+64][i],
// v[lane+96][i]}) used by matvec, sweep and judge — one LDS.128 replaces
// 4 scalar LDS in every serial chain link.
__global__ void __launch_bounds__(128) rnn_main_kernel(const float* __restrict__ inp,
                                                       const float* __restrict__ tgt_g,
                                                       const float* __restrict__ ret,
                                                       const float* __restrict__ W,
                                                       const float* __restrict__ b_g) {
    extern __shared__ float smem[];
    float* sv = smem;                          // v padded: [128][129]
    float* pvf = smem + D * SV_STRIDE;         // float4 row-quads: [128][32]
    float* xb = pvf + D * 32 * 4;              // per-warp x/u buffer: [4][128]

    int tid = threadIdx.x, lane = tid & 31, warp = tid >> 5;
    int col = blockIdx.x * 4 + warp;  // grid=128 -> col in [0,512)

    // ---- fused prep: thread tid row-normalizes row tid of W into smem.
    {
        const float* wr = W + (size_t)tid * D;
        float ss = 0.f;
#pragma unroll 8
        for (int j = 0; j < D; j++) ss += wr[j] * wr[j];
        float nrm = fmaxf(sqrtf(ss), 1e-12f);
        for (int j = 0; j < D; j++) sv[tid * SV_STRIDE + j] = wr[j] / nrm;
    }

    // h0 / params load overlapped with v setup
    float h4[4], tgt4[4], ab4[4], bp4[4], bn4[4];
#pragma unroll
    for (int q = 0; q < 4; q++) {
        int d = lane + 32 * q;
        tgt4[q] = tgt_g[d];
        ab4[q] = fabsf(b_g[d]);
        bp4[q] = ab4[q] + EPS;
        bn4[q] = -ab4[q] - EPS;
        float h0 = inp[(size_t)d * TB + col];  // input[:,0,:]
        h4[q] = h0;
        g_outT[(size_t)col * D + d] = h0;      // t = 0 slice
    }

    // prefetch r for step t=1 (returns[:,0,:])
    float rp4[4];
#pragma unroll
    for (int q = 0; q < 4; q++)
        rp4[q] = ret[(size_t)(lane + 32 * q) * TB + col];

    __syncthreads();  // sv complete

    // ---- build packed row-quad copy for matvec/sweep/judge
    float4* pv4 = (float4*)pvf;
    for (int idx = tid; idx < D * 32; idx += 128) {
        int i = idx >> 5, l = idx & 31;
        pv4[idx] = make_float4(sv[l * SV_STRIDE + i],
                               sv[(l + 32) * SV_STRIDE + i],
                               sv[(l + 64) * SV_STRIDE + i],
                               sv[(l + 96) * SV_STRIDE + i]);
    }

    float rvd4[4];
#pragma unroll
    for (int q = 0; q < 4; q++) {
        int d = lane + 32 * q;
        rvd4[q] = 1.0f / sv[d * SV_STRIDE + d];
    }

    __syncthreads();  // pv ready

    float* xw = xb + warp * D;
    const float4* xw4 = (const float4*)xw;

    // packed matvec chunk: 4 x-quads (16 columns) starting at i4=base
    float vu0, vu1, vu2, vu3;
    auto mv_chunk = [&](int base) {
#pragma unroll
        for (int i4 = base; i4 < base + 4; i4++) {
            float4 x = xw4[i4];
            int i = 4 * i4;
#pragma unroll
            for (int u = 0; u < 4; u++) {
                float xi = (u == 0) ? x.x : (u == 1) ? x.y : (u == 2) ? x.z : x.w;
                float4 vv = pv4[(i + u) * 32 + lane];
                vu0 = fmaf(vv.x, xi, vu0);
                vu1 = fmaf(vv.y, xi, vu1);
                vu2 = fmaf(vv.z, xi, vu2);
                vu3 = fmaf(vv.w, xi, vu3);
            }
        }
    };

    // ---- one-time vt = v @ tgt (same code path as the step matvec)
    float vt4[4];
    {
#pragma unroll
        for (int q = 0; q < 4; q++) xw[lane + 32 * q] = tgt4[q];
        __syncwarp();
        vu0 = vu1 = vu2 = vu3 = 0.f;
        for (int c = 0; c < 32; c += 4) mv_chunk(c);
        vt4[0] = vu0; vt4[1] = vu1; vt4[2] = vu2; vt4[3] = vu3;
        __syncwarp();
    }

    for (int t = 1; t < T; t++) {
        // ---- u = h*(1+r); acc = sum(h*r) (reduction deferred into matvec) ----
        float r4[4], u4[4];
        float red = 0.f;
#pragma unroll
        for (int q = 0; q < 4; q++) {
            r4[q] = rp4[q];
            red += h4[q] * r4[q];
            u4[q] = h4[q] * (1.0f + r4[q]);
            xw[lane + 32 * q] = u4[q];
        }
        __syncwarp();

        // prefetch next step's r while the matvec runs
        if (t < T - 1) {
#pragma unroll
            for (int q = 0; q < 4; q++)
                rp4[q] = ret[(size_t)(lane + 32 * q) * TB + (size_t)t * BATCH + col];
        }

        // ---- matvec on u with the shfl reduction interleaved between chunks
        vu0 = vu1 = vu2 = vu3 = 0.f;
        mv_chunk(0);
        red += __shfl_xor_sync(FULLMASK, red, 16);
        mv_chunk(4);
        red += __shfl_xor_sync(FULLMASK, red, 8);
        mv_chunk(8);
        red += __shfl_xor_sync(FULLMASK, red, 4);
        mv_chunk(12);
        red += __shfl_xor_sync(FULLMASK, red, 2);
        mv_chunk(16);
        red += __shfl_xor_sync(FULLMASK, red, 1);
        mv_chunk(20);
        float inv = 1.0f / (1.0f + red);
        mv_chunk(24);
        mv_chunk(28);
        __syncwarp();  // xw reads done before next-iteration writes

        // s = inv*(v@u) - v@tgt ; adj = u*inv ; x = adj - tgt
        float s4[4], adj4[4], x4[4];
        s4[0] = fmaf(vu0, inv, -vt4[0]);
        s4[1] = fmaf(vu1, inv, -vt4[1]);
        s4[2] = fmaf(vu2, inv, -vt4[2]);
        s4[3] = fmaf(vu3, inv, -vt4[3]);
#pragma unroll
        for (int q = 0; q < 4; q++) {
            adj4[q] = u4[q] * inv;
            x4[q] = adj4[q] - tgt4[q];
        }

        // ---- delta + feas0 ----
        float del4[4];
        bool loc = true;
#pragma unroll
        for (int q = 0; q < 4; q++) {
            float s = s4[q];
            float num = 0.f;
            if (s > ab4[q]) num = ab4[q] - s;
            else if (s < -ab4[q]) num = -ab4[q] - s;
            del4[q] = num * rvd4[q];
            loc = loc && (s < bp4[q]) && (s > bn4[q]);
        }
        bool feas0 = __all_sync(FULLMASK, loc);
        bool judge = feas0;

        // ---- judge: any single-coordinate fix feasible? ----
        if (!judge) {
            unsigned mm[4];
            int ncand = 0;
#pragma unroll
            for (int sl = 0; sl < 4; sl++) {
                mm[sl] = __ballot_sync(FULLMASK, del4[sl] != 0.f);
                ncand += __popc(mm[sl]);
            }

            if (ncand > 3) {
                // ---- exact screen against one maximally-violated coordinate k*.
                float mv = 0.f;
#pragma unroll
                for (int q = 0; q < 4; q++)
                    mv = fmaxf(mv, fabsf(s4[q]) - ab4[q]);
                float wv = mv;
#pragma unroll
                for (int o = 16; o; o >>= 1)
                    wv = fmaxf(wv, __shfl_xor_sync(FULLMASK, wv, o));
                int myq = -1;
#pragma unroll
                for (int q = 0; q < 4; q++)
                    if (fabsf(s4[q]) - ab4[q] == wv) myq = q;
                unsigned own = __ballot_sync(FULLMASK, myq >= 0);
                int ln = __ffs(own) - 1;
                int qs = __shfl_sync(FULLMASK, myq, ln);  // uniform slot of k*
                float sA = (qs == 0) ? s4[0] : (qs == 1) ? s4[1] : (qs == 2) ? s4[2] : s4[3];
                float pA = (qs == 0) ? bp4[0] : (qs == 1) ? bp4[1] : (qs == 2) ? bp4[2] : bp4[3];
                float nA = (qs == 0) ? bn4[0] : (qs == 1) ? bn4[1] : (qs == 2) ? bn4[2] : bn4[3];
                float sstar = __shfl_sync(FULLMASK, sA, ln);
                float bpst = __shfl_sync(FULLMASK, pA, ln);
                float bnst = __shfl_sync(FULLMASK, nA, ln);
                int kstar = qs * 32 + ln;
                const float* rowk = sv + (size_t)kstar * SV_STRIDE;
#pragma unroll
                for (int sl = 0; sl < 4; sl++) {
                    float sn = fmaf(rowk[lane + 32 * sl], del4[sl], sstar);
                    bool okc = (del4[sl] != 0.f) && (sn < bpst) && (sn > bnst);
                    mm[sl] = __ballot_sync(FULLMASK, okc);
                }
            }

            // serial full test over (screened) survivors — unchanged semantics,
            // one LDS.128 per candidate instead of 4 scalar LDS.
#pragma unroll
            for (int sl = 0; sl < 4; sl++) {
                if (judge) continue;
                unsigned mask = mm[sl];
                while (mask) {
                    int ln = __ffs(mask) - 1;
                    mask &= mask - 1;
                    float di = __shfl_sync(FULLMASK, del4[sl], ln);
                    int i = sl * 32 + ln;
                    float4 vi = pv4[i * 32 + lane];
                    float sn0 = fmaf(vi.x, di, s4[0]);
                    float sn1 = fmaf(vi.y, di, s4[1]);
                    float sn2 = fmaf(vi.z, di, s4[2]);
                    float sn3 = fmaf(vi.w, di, s4[3]);
                    bool ok = (sn0 < bp4[0]) && (sn0 > bn4[0])
                           && (sn1 < bp4[1]) && (sn1 > bn4[1])
                           && (sn2 < bp4[2]) && (sn2 > bn4[2])
                           && (sn3 < bp4[3]) && (sn3 > bn4[3]);
                    if (__all_sync(FULLMASK, ok)) { judge = true; break; }
                }
            }
        }

        float hres4[4];
        if (judge) {
            if (feas0) {
#pragma unroll
                for (int q = 0; q < 4; q++) hres4[q] = adj4[q];
            } else {
                // ---- Gauss-Seidel sweep: ballot-driven, exact vs reference's
                // strictly-increasing single pass; LDS.128 per fired coordinate.
                float ssl[4], ht4[4];
#pragma unroll
                for (int q = 0; q < 4; q++) { ssl[q] = s4[q]; ht4[q] = adj4[q]; }
#pragma unroll
                for (int sl = 0; sl < 4; sl++) {
                    unsigned eligible = FULLMASK;
                    while (true) {
                        float s = ssl[sl];
                        float num = 0.f;
                        if (s > ab4[sl]) num = ab4[sl] - s;
                        else if (s < -ab4[sl]) num = -ab4[sl] - s;
                        unsigned mask = __ballot_sync(FULLMASK, num != 0.f) & eligible;
                        if (!mask) break;
                        int ln = __ffs(mask) - 1;
                        float cand = num * rvd4[sl];
                        float dj = __shfl_sync(FULLMASK, cand, ln);
                        int j = sl * 32 + ln;
                        float4 vj = pv4[j * 32 + lane];
                        ssl[0] = fmaf(vj.x, dj, ssl[0]);
                        ssl[1] = fmaf(vj.y, dj, ssl[1]);
                        ssl[2] = fmaf(vj.z, dj, ssl[2]);
                        ssl[3] = fmaf(vj.w, dj, ssl[3]);
                        if (lane == ln) ht4[sl] += dj;
                        eligible = (ln == 31) ? 0u : (FULLMASK << (ln + 1));
                    }
                }
#pragma unroll
                for (int q = 0; q < 4; q++) hres4[q] = ht4[q];
            }
        } else {
            // ---- bisection collapsed to scalar alpha on segment pi + a*(h-pi)
            float am = __int_as_float(0x7f800000);  // +inf
#pragma unroll
            for (int q = 0; q < 4; q++) {
                float as = fabsf(s4[q]);
                float lim = (as > 0.f) ? bp4[q] / as : __int_as_float(0x7f800000);
                am = fminf(am, lim);
            }
#pragma unroll
            for (int o = 16; o; o >>= 1)
                am = fminf(am, __shfl_xor_sync(FULLMASK, am, o));
            float ain = 0.f, aout = 1.f, amid = 0.5f;
#pragma unroll
            for (int it = 0; it < 10; it++) {
                amid = ain + (aout - ain) * 0.5f;
                if (amid <= am) ain = amid; else aout = amid;
            }
#pragma unroll
            for (int q = 0; q < 4; q++)
                hres4[q] = fmaf(amid, x4[q], tgt4[q]);
        }

#pragma unroll
        for (int q = 0; q < 4; q++) {
            h4[q] = hres4[q];
            g_outT[((size_t)t * BATCH + col) * D + (lane + 32 * q)] = hres4[q];
        }
    }
}

extern "C" void kernel_launch(void* const* d_in, const int* in_sizes, int n_in,
                              void* d_out, int out_size) {
    const float* inp = (const float*)d_in[0];   // (D,T,B)
    const float* tgt = (const float*)d_in[1];   // (D,)
    const float* ret = (const float*)d_in[2];   // (D,T,B)
    // d_in[3] = hidden (unused by reference)
    const float* W = (const float*)d_in[4];     // (D,D)
    const float* bb = (const float*)d_in[5];    // (D,)
    float* out = (float*)d_out;                 // D*T*B output + D*B h_last

    size_t smem_bytes =
        (size_t)(D * SV_STRIDE + D * 32 * 4 + 4 * D) * sizeof(float);
    cudaFuncSetAttribute(rnn_main_kernel,
                         cudaFuncAttributeMaxDynamicSharedMemorySize,
                         (int)smem_bytes);
    rnn_main_kernel<<<128, 128, smem_bytes>>>(inp, tgt, ret, W, bb);

    dim3 tb(32, 8);
    transpose_out_kernel<<<dim3(BATCH / 32, D / 32, T), tb>>>(out);
}

// round 16
// speedup vs baseline: 1.1130x; 1.1130x over previous
#include <cuda_runtime.h>
#include <math.h>

#define D 128
#define T 64
#define BATCH 512
#define EPS 1e-5f
#define FULLMASK 0xffffffffu

#define SV_STRIDE 129   // conflict-free rows AND columns (129 mod 32 = 1)
#define TB (T * BATCH)

// -------- scratch (device globals; no allocation allowed) --------
__device__ float g_outT[T * BATCH * D];      // output transposed: [t][b][d]

// -------- transpose outT [t][b][d] -> out (D,T,B); also emit h_last --------
__global__ void transpose_out_kernel(float* __restrict__ out) {
    __shared__ float tile[32][33];
    int t = blockIdx.z;
    int b0 = blockIdx.x * 32, d0 = blockIdx.y * 32;
    int tx = threadIdx.x, ty = threadIdx.y;
    const float* src = g_outT + (size_t)t * BATCH * D;
#pragma unroll
    for (int i = 0; i < 32; i += 8)
        tile[ty + i][tx] = src[(size_t)(b0 + ty + i) * D + (d0 + tx)];
    __syncthreads();
#pragma unroll
    for (int i = 0; i < 32; i += 8) {
        float val = tile[tx][ty + i];
        int d = d0 + ty + i;
        int b = b0 + tx;
        out[(size_t)d * TB + (size_t)t * BATCH + b] = val;
        if (t == T - 1)
            out[(size_t)D * TB + (size_t)d * BATCH + b] = val;
    }
}

// -------- main recurrence: 1 warp per batch column, thread owns 4 dims.
// Warps independent (no block barriers in hot loop). Matvec uses packed
// float2 row-pair loads (pv01/pv23 — LDS.64, NOT LDS.128: float4 forms
// regressed twice from register-quad pressure); the shfl reduction is
// interleaved between matvec chunks. Sweep/judge chain links also use the
// float2 pairs (2 LDS.64 instead of 4 scalar LDS per event).
__global__ void __launch_bounds__(128) rnn_main_kernel(const float* __restrict__ inp,
                                                       const float* __restrict__ tgt_g,
                                                       const float* __restrict__ ret,
                                                       const float* __restrict__ W,
                                                       const float* __restrict__ b_g) {
    extern __shared__ float smem[];
    float* sv = smem;                          // v padded: [128][129]
    float* pv01 = smem + D * SV_STRIDE;        // float2 pairs rows (l, l+32): [128][32]
    float* pv23 = pv01 + D * 32 * 2;           // float2 pairs rows (l+64, l+96)
    float* xb = pv23 + D * 32 * 2;             // per-warp x/u buffer: [4][128]

    int tid = threadIdx.x, lane = tid & 31, warp = tid >> 5;
    int col = blockIdx.x * 4 + warp;  // grid=128 -> col in [0,512)

    // ---- fused prep: thread tid row-normalizes row tid of W into smem.
    {
        const float* wr = W + (size_t)tid * D;
        float ss = 0.f;
#pragma unroll 8
        for (int j = 0; j < D; j++) ss += wr[j] * wr[j];
        float nrm = fmaxf(sqrtf(ss), 1e-12f);
        for (int j = 0; j < D; j++) sv[tid * SV_STRIDE + j] = wr[j] / nrm;
    }

    // h0 / params load overlapped with v setup
    float h4[4], tgt4[4], ab4[4], bp4[4], bn4[4];
#pragma unroll
    for (int q = 0; q < 4; q++) {
        int d = lane + 32 * q;
        tgt4[q] = tgt_g[d];
        ab4[q] = fabsf(b_g[d]);
        bp4[q] = ab4[q] + EPS;
        bn4[q] = -ab4[q] - EPS;
        float h0 = inp[(size_t)d * TB + col];  // input[:,0,:]
        h4[q] = h0;
        g_outT[(size_t)col * D + d] = h0;      // t = 0 slice
    }

    // prefetch r for step t=1 (returns[:,0,:])
    float rp4[4];
#pragma unroll
    for (int q = 0; q < 4; q++)
        rp4[q] = ret[(size_t)(lane + 32 * q) * TB + col];

    __syncthreads();  // sv complete

    // ---- build packed row-pair copies for matvec/sweep/judge
    for (int idx = tid; idx < D * 32; idx += 128) {
        int i = idx >> 5, l = idx & 31;
        ((float2*)pv01)[idx] = make_float2(sv[l * SV_STRIDE + i],
                                           sv[(l + 32) * SV_STRIDE + i]);
        ((float2*)pv23)[idx] = make_float2(sv[(l + 64) * SV_STRIDE + i],
                                           sv[(l + 96) * SV_STRIDE + i]);
    }

    float rvd4[4];
#pragma unroll
    for (int q = 0; q < 4; q++) {
        int d = lane + 32 * q;
        rvd4[q] = 1.0f / sv[d * SV_STRIDE + d];
    }

    __syncthreads();  // pv ready

    float* xw = xb + warp * D;
    const float4* xw4 = (const float4*)xw;
    const float2* p01 = (const float2*)pv01;
    const float2* p23 = (const float2*)pv23;

    // packed matvec chunk: 4 x-quads (16 columns) starting at i4=base
    float vu0, vu1, vu2, vu3;
    auto mv_chunk = [&](int base) {
#pragma unroll
        for (int i4 = base; i4 < base + 4; i4++) {
            float4 x = xw4[i4];
            int i = 4 * i4;
#pragma unroll
            for (int u = 0; u < 4; u++) {
                float xi = (u == 0) ? x.x : (u == 1) ? x.y : (u == 2) ? x.z : x.w;
                float2 a = p01[(i + u) * 32 + lane];
                float2 b = p23[(i + u) * 32 + lane];
                vu0 = fmaf(a.x, xi, vu0);
                vu1 = fmaf(a.y, xi, vu1);
                vu2 = fmaf(b.x, xi, vu2);
                vu3 = fmaf(b.y, xi, vu3);
            }
        }
    };

    // ---- one-time vt = v @ tgt (same code path as the step matvec)
    float vt4[4];
    {
#pragma unroll
        for (int q = 0; q < 4; q++) xw[lane + 32 * q] = tgt4[q];
        __syncwarp();
        vu0 = vu1 = vu2 = vu3 = 0.f;
        for (int c = 0; c < 32; c += 4) mv_chunk(c);
        vt4[0] = vu0; vt4[1] = vu1; vt4[2] = vu2; vt4[3] = vu3;
        __syncwarp();
    }

    for (int t = 1; t < T; t++) {
        // ---- u = h*(1+r); acc = sum(h*r) (reduction deferred into matvec) ----
        float r4[4], u4[4];
        float red = 0.f;
#pragma unroll
        for (int q = 0; q < 4; q++) {
            r4[q] = rp4[q];
            red += h4[q] * r4[q];
            u4[q] = h4[q] * (1.0f + r4[q]);
            xw[lane + 32 * q] = u4[q];
        }
        __syncwarp();

        // prefetch next step's r while the matvec runs
        if (t < T - 1) {
#pragma unroll
            for (int q = 0; q < 4; q++)
                rp4[q] = ret[(size_t)(lane + 32 * q) * TB + (size_t)t * BATCH + col];
        }

        // ---- matvec on u with the shfl reduction interleaved between chunks
        vu0 = vu1 = vu2 = vu3 = 0.f;
        mv_chunk(0);
        red += __shfl_xor_sync(FULLMASK, red, 16);
        mv_chunk(4);
        red += __shfl_xor_sync(FULLMASK, red, 8);
        mv_chunk(8);
        red += __shfl_xor_sync(FULLMASK, red, 4);
        mv_chunk(12);
        red += __shfl_xor_sync(FULLMASK, red, 2);
        mv_chunk(16);
        red += __shfl_xor_sync(FULLMASK, red, 1);
        mv_chunk(20);
        float inv = 1.0f / (1.0f + red);
        mv_chunk(24);
        mv_chunk(28);
        __syncwarp();  // xw reads done before next-iteration writes

        // s = inv*(v@u) - v@tgt ; adj = u*inv ; x = adj - tgt
        float s4[4], adj4[4], x4[4];
        s4[0] = fmaf(vu0, inv, -vt4[0]);
        s4[1] = fmaf(vu1, inv, -vt4[1]);
        s4[2] = fmaf(vu2, inv, -vt4[2]);
        s4[3] = fmaf(vu3, inv, -vt4[3]);
#pragma unroll
        for (int q = 0; q < 4; q++) {
            adj4[q] = u4[q] * inv;
            x4[q] = adj4[q] - tgt4[q];
        }

        // ---- delta + feas0 ----
        float del4[4];
        bool loc = true;
#pragma unroll
        for (int q = 0; q < 4; q++) {
            float s = s4[q];
            float num = 0.f;
            if (s > ab4[q]) num = ab4[q] - s;
            else if (s < -ab4[q]) num = -ab4[q] - s;
            del4[q] = num * rvd4[q];
            loc = loc && (s < bp4[q]) && (s > bn4[q]);
        }
        bool feas0 = __all_sync(FULLMASK, loc);
        bool judge = feas0;

        // ---- judge: any single-coordinate fix feasible? ----
        if (!judge) {
            unsigned mm[4];
            int ncand = 0;
#pragma unroll
            for (int sl = 0; sl < 4; sl++) {
                mm[sl] = __ballot_sync(FULLMASK, del4[sl] != 0.f);
                ncand += __popc(mm[sl]);
            }

            if (ncand > 3) {
                // ---- exact screen against one maximally-violated coordinate k*.
                float mv = 0.f;
#pragma unroll
                for (int q = 0; q < 4; q++)
                    mv = fmaxf(mv, fabsf(s4[q]) - ab4[q]);
                float wv = mv;
#pragma unroll
                for (int o = 16; o; o >>= 1)
                    wv = fmaxf(wv, __shfl_xor_sync(FULLMASK, wv, o));
                int myq = -1;
#pragma unroll
                for (int q = 0; q < 4; q++)
                    if (fabsf(s4[q]) - ab4[q] == wv) myq = q;
                unsigned own = __ballot_sync(FULLMASK, myq >= 0);
                int ln = __ffs(own) - 1;
                int qs = __shfl_sync(FULLMASK, myq, ln);  // uniform slot of k*
                float sA = (qs == 0) ? s4[0] : (qs == 1) ? s4[1] : (qs == 2) ? s4[2] : s4[3];
                float pA = (qs == 0) ? bp4[0] : (qs == 1) ? bp4[1] : (qs == 2) ? bp4[2] : bp4[3];
                float nA = (qs == 0) ? bn4[0] : (qs == 1) ? bn4[1] : (qs == 2) ? bn4[2] : bn4[3];
                float sstar = __shfl_sync(FULLMASK, sA, ln);
                float bpst = __shfl_sync(FULLMASK, pA, ln);
                float bnst = __shfl_sync(FULLMASK, nA, ln);
                int kstar = qs * 32 + ln;
                const float* rowk = sv + (size_t)kstar * SV_STRIDE;
#pragma unroll
                for (int sl = 0; sl < 4; sl++) {
                    float sn = fmaf(rowk[lane + 32 * sl], del4[sl], sstar);
                    bool okc = (del4[sl] != 0.f) && (sn < bpst) && (sn > bnst);
                    mm[sl] = __ballot_sync(FULLMASK, okc);
                }
            }

            // serial full test over (screened) survivors — unchanged semantics,
            // 2 LDS.64 per candidate instead of 4 scalar LDS.
#pragma unroll
            for (int sl = 0; sl < 4; sl++) {
                if (judge) continue;
                unsigned mask = mm[sl];
                while (mask) {
                    int ln = __ffs(mask) - 1;
                    mask &= mask - 1;
                    float di = __shfl_sync(FULLMASK, del4[sl], ln);
                    int i = sl * 32 + ln;
                    float2 a = p01[i * 32 + lane];
                    float2 b = p23[i * 32 + lane];
                    float sn0 = fmaf(a.x, di, s4[0]);
                    float sn1 = fmaf(a.y, di, s4[1]);
                    float sn2 = fmaf(b.x, di, s4[2]);
                    float sn3 = fmaf(b.y, di, s4[3]);
                    bool ok = (sn0 < bp4[0]) && (sn0 > bn4[0])
                           && (sn1 < bp4[1]) && (sn1 > bn4[1])
                           && (sn2 < bp4[2]) && (sn2 > bn4[2])
                           && (sn3 < bp4[3]) && (sn3 > bn4[3]);
                    if (__all_sync(FULLMASK, ok)) { judge = true; break; }
                }
            }
        }

        float hres4[4];
        if (judge) {
            if (feas0) {
#pragma unroll
                for (int q = 0; q < 4; q++) hres4[q] = adj4[q];
            } else {
                // ---- Gauss-Seidel sweep: ballot-driven, exact vs reference's
                // strictly-increasing single pass; 2 LDS.64 per fired coordinate.
                float ssl[4], ht4[4];
#pragma unroll
                for (int q = 0; q < 4; q++) { ssl[q] = s4[q]; ht4[q] = adj4[q]; }
#pragma unroll
                for (int sl = 0; sl < 4; sl++) {
                    unsigned eligible = FULLMASK;
                    while (true) {
                        float s = ssl[sl];
                        float num = 0.f;
                        if (s > ab4[sl]) num = ab4[sl] - s;
                        else if (s < -ab4[sl]) num = -ab4[sl] - s;
                        unsigned mask = __ballot_sync(FULLMASK, num != 0.f) & eligible;
                        if (!mask) break;
                        int ln = __ffs(mask) - 1;
                        float cand = num * rvd4[sl];
                        float dj = __shfl_sync(FULLMASK, cand, ln);
                        int j = sl * 32 + ln;
                        float2 a = p01[j * 32 + lane];
                        float2 b = p23[j * 32 + lane];
                        ssl[0] = fmaf(a.x, dj, ssl[0]);
                        ssl[1] = fmaf(a.y, dj, ssl[1]);
                        ssl[2] = fmaf(b.x, dj, ssl[2]);
                        ssl[3] = fmaf(b.y, dj, ssl[3]);
                        if (lane == ln) ht4[sl] += dj;
                        eligible = (ln == 31) ? 0u : (FULLMASK << (ln + 1));
                    }
                }
#pragma unroll
                for (int q = 0; q < 4; q++) hres4[q] = ht4[q];
            }
        } else {
            // ---- bisection collapsed to scalar alpha on segment pi + a*(h-pi)
            float am = __int_as_float(0x7f800000);  // +inf
#pragma unroll
            for (int q = 0; q < 4; q++) {
                float as = fabsf(s4[q]);
                float lim = (as > 0.f) ? bp4[q] / as : __int_as_float(0x7f800000);
                am = fminf(am, lim);
            }
#pragma unroll
            for (int o = 16; o; o >>= 1)
                am = fminf(am, __shfl_xor_sync(FULLMASK, am, o));
            float ain = 0.f, aout = 1.f, amid = 0.5f;
#pragma unroll
            for (int it = 0; it < 10; it++) {
                amid = ain + (aout - ain) * 0.5f;
                if (amid <= am) ain = amid; else aout = amid;
            }
#pragma unroll
            for (int q = 0; q < 4; q++)
                hres4[q] = fmaf(amid, x4[q], tgt4[q]);
        }

#pragma unroll
        for (int q = 0; q < 4; q++) {
            h4[q] = hres4[q];
            g_outT[((size_t)t * BATCH + col) * D + (lane + 32 * q)] = hres4[q];
        }
    }
}

extern "C" void kernel_launch(void* const* d_in, const int* in_sizes, int n_in,
                              void* d_out, int out_size) {
    const float* inp = (const float*)d_in[0];   // (D,T,B)
    const float* tgt = (const float*)d_in[1];   // (D,)
    const float* ret = (const float*)d_in[2];   // (D,T,B)
    // d_in[3] = hidden (unused by reference)
    const float* W = (const float*)d_in[4];     // (D,D)
    const float* bb = (const float*)d_in[5];    // (D,)
    float* out = (float*)d_out;                 // D*T*B output + D*B h_last

    size_t smem_bytes =
        (size_t)(D * SV_STRIDE + 2 * D * 32 * 2 + 4 * D) * sizeof(float);
    cudaFuncSetAttribute(rnn_main_kernel,
                         cudaFuncAttributeMaxDynamicSharedMemorySize,
                         (int)smem_bytes);
    rnn_main_kernel<<<128, 128, smem_bytes>>>(inp, tgt, ret, W, bb);

    dim3 tb(32, 8);
    transpose_out_kernel<<<dim3(BATCH / 32, D / 32, T), tb>>>(out);
}

// round 17
// speedup vs baseline: 1.2588x; 1.1310x over previous
#include <cuda_runtime.h>
#include <math.h>

#define D 128
#define T 64
#define BATCH 512
#define EPS 1e-5f
#define FULLMASK 0xffffffffu

#define SV_STRIDE 129   // conflict-free rows AND columns (129 mod 32 = 1)
#define TB (T * BATCH)

// -------- scratch (device globals; no allocation allowed) --------
__device__ float g_outT[T * BATCH * D];      // output transposed: [t][b][d]

// -------- transpose outT [t][b][d] -> out (D,T,B); also emit h_last --------
__global__ void transpose_out_kernel(float* __restrict__ out) {
    __shared__ float tile[32][33];
    int t = blockIdx.z;
    int b0 = blockIdx.x * 32, d0 = blockIdx.y * 32;
    int tx = threadIdx.x, ty = threadIdx.y;
    const float* src = g_outT + (size_t)t * BATCH * D;
#pragma unroll
    for (int i = 0; i < 32; i += 8)
        tile[ty + i][tx] = src[(size_t)(b0 + ty + i) * D + (d0 + tx)];
    __syncthreads();
#pragma unroll
    for (int i = 0; i < 32; i += 8) {
        float val = tile[tx][ty + i];
        int d = d0 + ty + i;
        int b = b0 + tx;
        out[(size_t)d * TB + (size_t)t * BATCH + b] = val;
        if (t == T - 1)
            out[(size_t)D * TB + (size_t)d * BATCH + b] = val;
    }
}

// -------- main recurrence: 1 warp per batch column, thread owns 4 dims.
// Warps independent (no block barriers in hot loop). Matvec uses packed
// float2 row-pair loads (LDS.64, NOT LDS.128 — float4 regressed twice);
// shfl reduction interleaved between matvec chunks. Screen pivot = FIRST
// violated coordinate (exact for any violated pivot; avoids the max tree).
__global__ void __launch_bounds__(128) rnn_main_kernel(const float* __restrict__ inp,
                                                       const float* __restrict__ tgt_g,
                                                       const float* __restrict__ ret,
                                                       const float* __restrict__ W,
                                                       const float* __restrict__ b_g) {
    extern __shared__ float smem[];
    float* sv = smem;                          // v padded: [128][129]
    float* pv01 = smem + D * SV_STRIDE;        // float2 pairs rows (l, l+32): [128][32]
    float* pv23 = pv01 + D * 32 * 2;           // float2 pairs rows (l+64, l+96)
    float* xb = pv23 + D * 32 * 2;             // per-warp x/u buffer: [4][128]

    int tid = threadIdx.x, lane = tid & 31, warp = tid >> 5;
    int col = blockIdx.x * 4 + warp;  // grid=128 -> col in [0,512)

    // ---- fused prep: thread tid row-normalizes row tid of W into smem.
    {
        const float* wr = W + (size_t)tid * D;
        float ss = 0.f;
#pragma unroll 8
        for (int j = 0; j < D; j++) ss += wr[j] * wr[j];
        float nrm = fmaxf(sqrtf(ss), 1e-12f);
        for (int j = 0; j < D; j++) sv[tid * SV_STRIDE + j] = wr[j] / nrm;
    }

    // h0 / params load overlapped with v setup
    float h4[4], tgt4[4], ab4[4], bp4[4], bn4[4];
#pragma unroll
    for (int q = 0; q < 4; q++) {
        int d = lane + 32 * q;
        tgt4[q] = tgt_g[d];
        ab4[q] = fabsf(b_g[d]);
        bp4[q] = ab4[q] + EPS;
        bn4[q] = -ab4[q] - EPS;
        float h0 = inp[(size_t)d * TB + col];  // input[:,0,:]
        h4[q] = h0;
        g_outT[(size_t)col * D + d] = h0;      // t = 0 slice
    }

    // prefetch r for step t=1 (returns[:,0,:])
    float rp4[4];
#pragma unroll
    for (int q = 0; q < 4; q++)
        rp4[q] = ret[(size_t)(lane + 32 * q) * TB + col];

    __syncthreads();  // sv complete

    // ---- build packed row-pair copies for matvec/sweep/judge
    for (int idx = tid; idx < D * 32; idx += 128) {
        int i = idx >> 5, l = idx & 31;
        ((float2*)pv01)[idx] = make_float2(sv[l * SV_STRIDE + i],
                                           sv[(l + 32) * SV_STRIDE + i]);
        ((float2*)pv23)[idx] = make_float2(sv[(l + 64) * SV_STRIDE + i],
                                           sv[(l + 96) * SV_STRIDE + i]);
    }

    float rvd4[4];
#pragma unroll
    for (int q = 0; q < 4; q++) {
        int d = lane + 32 * q;
        rvd4[q] = 1.0f / sv[d * SV_STRIDE + d];
    }

    __syncthreads();  // pv ready

    float* xw = xb + warp * D;
    const float4* xw4 = (const float4*)xw;
    const float2* p01 = (const float2*)pv01;
    const float2* p23 = (const float2*)pv23;

    // packed matvec chunk: 4 x-quads (16 columns) starting at i4=base
    float vu0, vu1, vu2, vu3;
    auto mv_chunk = [&](int base) {
#pragma unroll
        for (int i4 = base; i4 < base + 4; i4++) {
            float4 x = xw4[i4];
            int i = 4 * i4;
#pragma unroll
            for (int u = 0; u < 4; u++) {
                float xi = (u == 0) ? x.x : (u == 1) ? x.y : (u == 2) ? x.z : x.w;
                float2 a = p01[(i + u) * 32 + lane];
                float2 b = p23[(i + u) * 32 + lane];
                vu0 = fmaf(a.x, xi, vu0);
                vu1 = fmaf(a.y, xi, vu1);
                vu2 = fmaf(b.x, xi, vu2);
                vu3 = fmaf(b.y, xi, vu3);
            }
        }
    };

    // ---- one-time vt = v @ tgt (same code path as the step matvec)
    float vt4[4];
    {
#pragma unroll
        for (int q = 0; q < 4; q++) xw[lane + 32 * q] = tgt4[q];
        __syncwarp();
        vu0 = vu1 = vu2 = vu3 = 0.f;
        for (int c = 0; c < 32; c += 4) mv_chunk(c);
        vt4[0] = vu0; vt4[1] = vu1; vt4[2] = vu2; vt4[3] = vu3;
        __syncwarp();
    }

    for (int t = 1; t < T; t++) {
        // ---- u = h*(1+r); acc = sum(h*r) (reduction deferred into matvec) ----
        float r4[4], u4[4];
        float red = 0.f;
#pragma unroll
        for (int q = 0; q < 4; q++) {
            r4[q] = rp4[q];
            red += h4[q] * r4[q];
            u4[q] = h4[q] * (1.0f + r4[q]);
            xw[lane + 32 * q] = u4[q];
        }
        __syncwarp();

        // prefetch next step's r while the matvec runs
        if (t < T - 1) {
#pragma unroll
            for (int q = 0; q < 4; q++)
                rp4[q] = ret[(size_t)(lane + 32 * q) * TB + (size_t)t * BATCH + col];
        }

        // ---- matvec on u with the shfl reduction interleaved between chunks
        vu0 = vu1 = vu2 = vu3 = 0.f;
        mv_chunk(0);
        red += __shfl_xor_sync(FULLMASK, red, 16);
        mv_chunk(4);
        red += __shfl_xor_sync(FULLMASK, red, 8);
        mv_chunk(8);
        red += __shfl_xor_sync(FULLMASK, red, 4);
        mv_chunk(12);
        red += __shfl_xor_sync(FULLMASK, red, 2);
        mv_chunk(16);
        red += __shfl_xor_sync(FULLMASK, red, 1);
        mv_chunk(20);
        float inv = 1.0f / (1.0f + red);
        mv_chunk(24);
        mv_chunk(28);
        __syncwarp();  // xw reads done before next-iteration writes

        // s = inv*(v@u) - v@tgt ; adj = u*inv ; x = adj - tgt
        float s4[4], adj4[4], x4[4];
        s4[0] = fmaf(vu0, inv, -vt4[0]);
        s4[1] = fmaf(vu1, inv, -vt4[1]);
        s4[2] = fmaf(vu2, inv, -vt4[2]);
        s4[3] = fmaf(vu3, inv, -vt4[3]);
#pragma unroll
        for (int q = 0; q < 4; q++) {
            adj4[q] = u4[q] * inv;
            x4[q] = adj4[q] - tgt4[q];
        }

        // ---- delta + per-slot violation ballots (feas0 falls out uniform) ----
        float del4[4];
        unsigned vm[4];
#pragma unroll
        for (int q = 0; q < 4; q++) {
            float s = s4[q];
            float num = 0.f;
            if (s > ab4[q]) num = ab4[q] - s;
            else if (s < -ab4[q]) num = -ab4[q] - s;
            del4[q] = num * rvd4[q];
            bool okq = (s < bp4[q]) && (s > bn4[q]);
            vm[q] = __ballot_sync(FULLMASK, !okq);
        }
        bool feas0 = (vm[0] | vm[1] | vm[2] | vm[3]) == 0u;
        bool judge = feas0;
        float am = __int_as_float(0x7f800000);  // bisection limit, hoisted

        // ---- judge: any single-coordinate fix feasible? ----
        if (!judge) {
            // hoisted am computation — independent chain, overlaps the screen
#pragma unroll
            for (int q = 0; q < 4; q++) {
                float as = fabsf(s4[q]);
                float lim = (as > 0.f) ? bp4[q] / as : __int_as_float(0x7f800000);
                am = fminf(am, lim);
            }
#pragma unroll
            for (int o = 16; o; o >>= 1)
                am = fminf(am, __shfl_xor_sync(FULLMASK, am, o));

            unsigned mm[4];
            int ncand = 0;
#pragma unroll
            for (int sl = 0; sl < 4; sl++) {
                mm[sl] = __ballot_sync(FULLMASK, del4[sl] != 0.f);
                ncand += __popc(mm[sl]);
            }

            if (ncand > 3) {
                // ---- exact screen against the FIRST violated coordinate k*.
                // Any violated pivot is exact: rejection uses the IDENTICAL
                // fmaf/compare the full test applies for coordinate k*.
                int qs = (vm[0]) ? 0 : (vm[1]) ? 1 : (vm[2]) ? 2 : 3;  // uniform
                unsigned vmq = (qs == 0) ? vm[0] : (qs == 1) ? vm[1]
                             : (qs == 2) ? vm[2] : vm[3];
                int ln = __ffs(vmq) - 1;
                float sA = (qs == 0) ? s4[0] : (qs == 1) ? s4[1] : (qs == 2) ? s4[2] : s4[3];
                float pA = (qs == 0) ? bp4[0] : (qs == 1) ? bp4[1] : (qs == 2) ? bp4[2] : bp4[3];
                float nA = (qs == 0) ? bn4[0] : (qs == 1) ? bn4[1] : (qs == 2) ? bn4[2] : bn4[3];
                float sstar = __shfl_sync(FULLMASK, sA, ln);
                float bpst = __shfl_sync(FULLMASK, pA, ln);
                float bnst = __shfl_sync(FULLMASK, nA, ln);
                int kstar = qs * 32 + ln;
                const float* rowk = sv + (size_t)kstar * SV_STRIDE;
#pragma unroll
                for (int sl = 0; sl < 4; sl++) {
                    float sn = fmaf(rowk[lane + 32 * sl], del4[sl], sstar);
                    bool okc = (del4[sl] != 0.f) && (sn < bpst) && (sn > bnst);
                    mm[sl] = __ballot_sync(FULLMASK, okc);
                }
            }

            // serial full test over (screened) survivors — unchanged semantics,
            // 2 LDS.64 per candidate.
#pragma unroll
            for (int sl = 0; sl < 4; sl++) {
                if (judge) continue;
                unsigned mask = mm[sl];
                while (mask) {
                    int ln = __ffs(mask) - 1;
                    mask &= mask - 1;
                    float di = __shfl_sync(FULLMASK, del4[sl], ln);
                    int i = sl * 32 + ln;
                    float2 a = p01[i * 32 + lane];
                    float2 b = p23[i * 32 + lane];
                    float sn0 = fmaf(a.x, di, s4[0]);
                    float sn1 = fmaf(a.y, di, s4[1]);
                    float sn2 = fmaf(b.x, di, s4[2]);
                    float sn3 = fmaf(b.y, di, s4[3]);
                    bool ok = (sn0 < bp4[0]) && (sn0 > bn4[0])
                           && (sn1 < bp4[1]) && (sn1 > bn4[1])
                           && (sn2 < bp4[2]) && (sn2 > bn4[2])
                           && (sn3 < bp4[3]) && (sn3 > bn4[3]);
                    if (__all_sync(FULLMASK, ok)) { judge = true; break; }
                }
            }
        }

        float hres4[4];
        if (judge) {
            if (feas0) {
#pragma unroll
                for (int q = 0; q < 4; q++) hres4[q] = adj4[q];
            } else {
                // ---- Gauss-Seidel sweep: ballot-driven, exact vs reference's
                // strictly-increasing single pass; 2 LDS.64 per fired coordinate.
                float ssl[4], ht4[4];
#pragma unroll
                for (int q = 0; q < 4; q++) { ssl[q] = s4[q]; ht4[q] = adj4[q]; }
#pragma unroll
                for (int sl = 0; sl < 4; sl++) {
                    unsigned eligible = FULLMASK;
                    while (true) {
                        float s = ssl[sl];
                        float num = 0.f;
                        if (s > ab4[sl]) num = ab4[sl] - s;
                        else if (s < -ab4[sl]) num = -ab4[sl] - s;
                        unsigned mask = __ballot_sync(FULLMASK, num != 0.f) & eligible;
                        if (!mask) break;
                        int ln = __ffs(mask) - 1;
                        float cand = num * rvd4[sl];
                        float dj = __shfl_sync(FULLMASK, cand, ln);
                        int j = sl * 32 + ln;
                        float2 a = p01[j * 32 + lane];
                        float2 b = p23[j * 32 + lane];
                        ssl[0] = fmaf(a.x, dj, ssl[0]);
                        ssl[1] = fmaf(a.y, dj, ssl[1]);
                        ssl[2] = fmaf(b.x, dj, ssl[2]);
                        ssl[3] = fmaf(b.y, dj, ssl[3]);
                        if (lane == ln) ht4[sl] += dj;
                        eligible = (ln == 31) ? 0u : (FULLMASK << (ln + 1));
                    }
                }
#pragma unroll
                for (int q = 0; q < 4; q++) hres4[q] = ht4[q];
            }
        } else {
            // ---- bisection collapsed to scalar alpha (am precomputed above)
            float ain = 0.f, aout = 1.f, amid = 0.5f;
#pragma unroll
            for (int it = 0; it < 10; it++) {
                amid = ain + (aout - ain) * 0.5f;
                if (amid <= am) ain = amid; else aout = amid;
            }
#pragma unroll
            for (int q = 0; q < 4; q++)
                hres4[q] = fmaf(amid, x4[q], tgt4[q]);
        }

#pragma unroll
        for (int q = 0; q < 4; q++) {
            h4[q] = hres4[q];
            g_outT[((size_t)t * BATCH + col) * D + (lane + 32 * q)] = hres4[q];
        }
    }
}

extern "C" void kernel_launch(void* const* d_in, const int* in_sizes, int n_in,
                              void* d_out, int out_size) {
    const float* inp = (const float*)d_in[0];   // (D,T,B)
    const float* tgt = (const float*)d_in[1];   // (D,)
    const float* ret = (const float*)d_in[2];   // (D,T,B)
    // d_in[3] = hidden (unused by reference)
    const float* W = (const float*)d_in[4];     // (D,D)
    const float* bb = (const float*)d_in[5];    // (D,)
    float* out = (float*)d_out;                 // D*T*B output + D*B h_last

    size_t smem_bytes =
        (size_t)(D * SV_STRIDE + 2 * D * 32 * 2 + 4 * D) * sizeof(float);
    cudaFuncSetAttribute(rnn_main_kernel,
                         cudaFuncAttributeMaxDynamicSharedMemorySize,
                         (int)smem_bytes);
    rnn_main_kernel<<<128, 128, smem_bytes>>>(inp, tgt, ret, W, bb);

    dim3 tb(32, 8);
    transpose_out_kernel<<<dim3(BATCH / 32, D / 32, T), tb>>>(out);
}